// round 6
// baseline (speedup 1.0000x reference)
#include <cuda_runtime.h>
#include <cstdint>

#define TT  12
#define NN  50000
#define EE  800000
#define TN  (TT*NN)          /* 600000 */
#define FIN 128
#define HH  64

// ------------------------- static device scratch -------------------------
__device__ float d_xw[(size_t)TN*64];          // xs @ W_gcn
__device__ float d_cur[(size_t)TN*64];         // GCN output
__device__ float d_gicur[(size_t)TN*192];      // cur @ W_ih[:, :64]^T
__device__ float d_hring[(size_t)3*NN*64];     // h ring buffer
__device__ float d_gring[3*NN];                // attention scalar ring
__device__ float d_dinv[TN];
__device__ int   d_cnt[TN];
__device__ int   d_fill[TN];
__device__ int   d_rowptr[TN];
__device__ int   d_ebuf[(size_t)TT*EE];
__device__ float d_WcT[64*192];                // [k][j] = W_ih[j][k]          (cur half)
__device__ float d_Ws [64*192];                // [k][j] = W_ih[j][64+k]       (short half)
__device__ float d_Qt [64*64];                 // [k][c] = Q[c][k]
__device__ int   d_bsum[1024];

// ------------------------- helpers -------------------------
__device__ __forceinline__ void ffma2(unsigned long long& d,
                                      unsigned long long a,
                                      unsigned long long b)
{
    asm("fma.rn.f32x2 %0, %1, %2, %0;" : "+l"(d) : "l"(a), "l"(b));
}

__device__ __forceinline__ float2 u2f2(unsigned long long u)
{
    float2 f;
    asm("mov.b64 {%0,%1}, %2;" : "=f"(f.x), "=f"(f.y) : "l"(u));
    return f;
}

__device__ __forceinline__ float sigf(float x)
{
    return 1.0f / (1.0f + __expf(-x));
}

// ------------------------- weight prep -------------------------
__global__ void k_prep(const float* __restrict__ W_ih, const float* __restrict__ Q,
                       float* __restrict__ WcT, float* __restrict__ Ws,
                       float* __restrict__ Qt)
{
    for (int i = threadIdx.x; i < 64*192; i += 256) {
        int k = i / 192, j = i % 192;
        WcT[(size_t)k*192 + j] = W_ih[(size_t)j*128 + k];
        Ws [(size_t)k*192 + j] = W_ih[(size_t)j*128 + 64 + k];
    }
    for (int i = threadIdx.x; i < 64*64; i += 256) {
        int k = i / 64, c = i % 64;
        Qt[(size_t)k*64 + c] = Q[(size_t)c*64 + k];
    }
}

// ------------------------- CSR build -------------------------
__global__ void k_count(const int* __restrict__ ei, int* __restrict__ cnt)
{
    int e = blockIdx.x*256 + threadIdx.x;
    int t = blockIdx.y;
    if (e < EE) {
        int dst = ei[(size_t)t*2*EE + EE + e];
        atomicAdd(&cnt[t*NN + dst], 1);
    }
}

__global__ void k_scan1(const int* __restrict__ cnt, int* __restrict__ incl,
                        int* __restrict__ bsum, int n)
{
    __shared__ int ws[32];
    int tid  = threadIdx.x;
    int i    = blockIdx.x*1024 + tid;
    int lane = tid & 31, wid = tid >> 5;
    int v = (i < n) ? cnt[i] : 0;
    int x = v;
#pragma unroll
    for (int o = 1; o < 32; o <<= 1) {
        int y = __shfl_up_sync(0xffffffffu, x, o);
        if (lane >= o) x += y;
    }
    if (lane == 31) ws[wid] = x;
    __syncthreads();
    if (wid == 0) {
        int s = ws[lane];
#pragma unroll
        for (int o = 1; o < 32; o <<= 1) {
            int y = __shfl_up_sync(0xffffffffu, s, o);
            if (lane >= o) s += y;
        }
        ws[lane] = s;
    }
    __syncthreads();
    if (wid > 0) x += ws[wid-1];
    if (i < n) incl[i] = x;
    if (tid == 1023) bsum[blockIdx.x] = x;
}

__global__ void k_scan2(int* __restrict__ bsum, int nb)
{
    __shared__ int ws[32];
    int tid  = threadIdx.x;
    int lane = tid & 31, wid = tid >> 5;
    int v = (tid < nb) ? bsum[tid] : 0;
    int x = v;
#pragma unroll
    for (int o = 1; o < 32; o <<= 1) {
        int y = __shfl_up_sync(0xffffffffu, x, o);
        if (lane >= o) x += y;
    }
    if (lane == 31) ws[wid] = x;
    __syncthreads();
    if (wid == 0) {
        int s = ws[lane];
#pragma unroll
        for (int o = 1; o < 32; o <<= 1) {
            int y = __shfl_up_sync(0xffffffffu, s, o);
            if (lane >= o) s += y;
        }
        ws[lane] = s;
    }
    __syncthreads();
    if (wid > 0) x += ws[wid-1];
    if (tid < nb) bsum[tid] = x - v;   // exclusive
}

__global__ void k_scan3(const int* __restrict__ cnt, int* __restrict__ incl_then_rowptr,
                        const int* __restrict__ bsum, int* __restrict__ fill,
                        float* __restrict__ dinv, int n)
{
    int i = blockIdx.x*1024 + threadIdx.x;
    if (i < n) {
        int c  = cnt[i];
        int ex = incl_then_rowptr[i] - c + bsum[blockIdx.x];
        incl_then_rowptr[i] = ex;
        fill[i] = ex;
        dinv[i] = rsqrtf(1.0f + (float)c);
    }
}

__global__ void k_fill(const int* __restrict__ ei, int* __restrict__ fill,
                       int* __restrict__ ebuf)
{
    int e = blockIdx.x*256 + threadIdx.x;
    int t = blockIdx.y;
    if (e < EE) {
        int src = ei[(size_t)t*2*EE + e];
        int dst = ei[(size_t)t*2*EE + EE + e];
        int pos = atomicAdd(&fill[t*NN + dst], 1);
        ebuf[pos] = t*NN + src;
    }
}

// ------------------------- gather (GCN aggregation) -------------------------
__global__ void k_gather(const float* __restrict__ xw, const float* __restrict__ bg,
                         float* __restrict__ cur,
                         const int* __restrict__ rowptr, const int* __restrict__ cnt,
                         const float* __restrict__ dinv, const int* __restrict__ ebuf)
{
    int w    = blockIdx.x*8 + (threadIdx.x >> 5);
    int lane = threadIdx.x & 31;
    if (w >= TN) return;
    int start = rowptr[w];
    int c     = cnt[w];
    int col   = 2*lane;
    float2 a0 = make_float2(0.f, 0.f), a1 = a0, a2 = a0, a3 = a0;
    for (int b0 = 0; b0 < c; b0 += 32) {
        int rem  = c - b0;
        int mcnt = rem < 32 ? rem : 32;
        int   idx = (lane < mcnt) ? ebuf[start + b0 + lane] : 0;
        float dv  = (lane < mcnt) ? dinv[idx] : 0.f;
        int e = 0;
        for (; e + 4 <= mcnt; e += 4) {
            int g0 = __shfl_sync(0xffffffffu, idx, e);
            int g1 = __shfl_sync(0xffffffffu, idx, e+1);
            int g2 = __shfl_sync(0xffffffffu, idx, e+2);
            int g3 = __shfl_sync(0xffffffffu, idx, e+3);
            float w0 = __shfl_sync(0xffffffffu, dv, e);
            float w1 = __shfl_sync(0xffffffffu, dv, e+1);
            float w2 = __shfl_sync(0xffffffffu, dv, e+2);
            float w3 = __shfl_sync(0xffffffffu, dv, e+3);
            float2 x0 = *(const float2*)&xw[(size_t)g0*64 + col];
            float2 x1 = *(const float2*)&xw[(size_t)g1*64 + col];
            float2 x2 = *(const float2*)&xw[(size_t)g2*64 + col];
            float2 x3 = *(const float2*)&xw[(size_t)g3*64 + col];
            a0.x += w0*x0.x; a0.y += w0*x0.y;
            a1.x += w1*x1.x; a1.y += w1*x1.y;
            a2.x += w2*x2.x; a2.y += w2*x2.y;
            a3.x += w3*x3.x; a3.y += w3*x3.y;
        }
        for (; e < mcnt; e++) {
            int   g  = __shfl_sync(0xffffffffu, idx, e);
            float wv = __shfl_sync(0xffffffffu, dv,  e);
            float2 x = *(const float2*)&xw[(size_t)g*64 + col];
            a0.x += wv*x.x; a0.y += wv*x.y;
        }
    }
    float ax = a0.x + a1.x + a2.x + a3.x;
    float ay = a0.y + a1.y + a2.y + a3.y;
    float ds = dinv[w];
    float2 s = *(const float2*)&xw[(size_t)w*64 + col];
    float2 o;
    o.x = ds*(ax + ds*s.x) + bg[col];
    o.y = ds*(ay + ds*s.y) + bg[col+1];
    *(float2*)&cur[(size_t)w*64 + col] = o;
}

// ------------------------- tiled GEMM (f32x2), conflict-free skewed smem -------------------------
#define BM 128
#define BN 64
#define BK 16
#define AIDX(r) (2*(r) + (((r) >> 3) << 2))
#define BIDX(c) ((c) + (((c) >> 3) << 2))

__global__ __launch_bounds__(128)
void k_gemm(const float* __restrict__ A, const float* __restrict__ B,
            float* __restrict__ C, int M, int K, int ldb)
{
    __shared__ __align__(16) float ATd[BK][320];   // duplicated + skewed
    __shared__ __align__(16) float Bs[BK][96];     // skewed
    int tid  = threadIdx.x;
    int row0 = blockIdx.x * BM;
    int nb   = blockIdx.y * BN;
    int r0   = (tid >> 3) * 8;     // 8 rows per thread
    int c0   = (tid & 7) * 8;      // 8 cols per thread
    unsigned long long acc[8][4];
#pragma unroll
    for (int r = 0; r < 8; r++)
#pragma unroll
        for (int q = 0; q < 4; q++) acc[r][q] = 0ull;

    for (int kk = 0; kk < K; kk += BK) {
        // A tile: thread loads its row (row0+tid), 16 k's as 4 float4, stores duplicated
        {
            int grow = row0 + tid;
            int ai   = AIDX(tid);
#pragma unroll
            for (int q = 0; q < 4; q++) {
                float4 v = make_float4(0.f, 0.f, 0.f, 0.f);
                if (grow < M) v = *(const float4*)&A[(size_t)grow*K + kk + q*4];
                *(float2*)&ATd[q*4+0][ai] = make_float2(v.x, v.x);
                *(float2*)&ATd[q*4+1][ai] = make_float2(v.y, v.y);
                *(float2*)&ATd[q*4+2][ai] = make_float2(v.z, v.z);
                *(float2*)&ATd[q*4+3][ai] = make_float2(v.w, v.w);
            }
        }
        // B tile (16 x 64)
        {
#pragma unroll
            for (int q = 0; q < 2; q++) {
                int idx = tid*2 + q;
                int kb  = idx >> 4;
                int cf  = (idx & 15) * 4;
                *(float4*)&Bs[kb][BIDX(cf)] = *(const float4*)&B[(size_t)(kk + kb)*ldb + nb + cf];
            }
        }
        __syncthreads();
        int ai = AIDX(r0);
        int bi = BIDX(c0);
#pragma unroll
        for (int k = 0; k < BK; k++) {
            ulonglong2 a0 = *(const ulonglong2*)&ATd[k][ai];
            ulonglong2 a1 = *(const ulonglong2*)&ATd[k][ai + 4];
            ulonglong2 a2 = *(const ulonglong2*)&ATd[k][ai + 8];
            ulonglong2 a3 = *(const ulonglong2*)&ATd[k][ai + 12];
            ulonglong2 b0 = *(const ulonglong2*)&Bs[k][bi];
            ulonglong2 b1 = *(const ulonglong2*)&Bs[k][bi + 4];
            ffma2(acc[0][0], a0.x, b0.x); ffma2(acc[0][1], a0.x, b0.y);
            ffma2(acc[0][2], a0.x, b1.x); ffma2(acc[0][3], a0.x, b1.y);
            ffma2(acc[1][0], a0.y, b0.x); ffma2(acc[1][1], a0.y, b0.y);
            ffma2(acc[1][2], a0.y, b1.x); ffma2(acc[1][3], a0.y, b1.y);
            ffma2(acc[2][0], a1.x, b0.x); ffma2(acc[2][1], a1.x, b0.y);
            ffma2(acc[2][2], a1.x, b1.x); ffma2(acc[2][3], a1.x, b1.y);
            ffma2(acc[3][0], a1.y, b0.x); ffma2(acc[3][1], a1.y, b0.y);
            ffma2(acc[3][2], a1.y, b1.x); ffma2(acc[3][3], a1.y, b1.y);
            ffma2(acc[4][0], a2.x, b0.x); ffma2(acc[4][1], a2.x, b0.y);
            ffma2(acc[4][2], a2.x, b1.x); ffma2(acc[4][3], a2.x, b1.y);
            ffma2(acc[5][0], a2.y, b0.x); ffma2(acc[5][1], a2.y, b0.y);
            ffma2(acc[5][2], a2.y, b1.x); ffma2(acc[5][3], a2.y, b1.y);
            ffma2(acc[6][0], a3.x, b0.x); ffma2(acc[6][1], a3.x, b0.y);
            ffma2(acc[6][2], a3.x, b1.x); ffma2(acc[6][3], a3.x, b1.y);
            ffma2(acc[7][0], a3.y, b0.x); ffma2(acc[7][1], a3.y, b0.y);
            ffma2(acc[7][2], a3.y, b1.x); ffma2(acc[7][3], a3.y, b1.y);
        }
        __syncthreads();
    }
#pragma unroll
    for (int r = 0; r < 8; r++) {
        int grow = row0 + r0 + r;
        if (grow < M) {
            float2 p0 = u2f2(acc[r][0]);
            float2 p1 = u2f2(acc[r][1]);
            float2 p2 = u2f2(acc[r][2]);
            float2 p3 = u2f2(acc[r][3]);
            *(float4*)&C[(size_t)grow*ldb + nb + c0]     = make_float4(p0.x, p0.y, p1.x, p1.y);
            *(float4*)&C[(size_t)grow*ldb + nb + c0 + 4] = make_float4(p2.x, p2.y, p3.x, p3.y);
        }
    }
}

// ------------------------- fused step kernel (persistent, weights in smem) -------------------------
// smem layout (floats): sW[64*192] | sQ[64*64] | sd[64*68] | hd[64*68]
#define SMF_SW  0
#define SMF_SQ  12288
#define SMF_SD  (12288 + 4096)
#define SMF_HD  (12288 + 4096 + 4352)
#define SMF_TOT (12288 + 4096 + 4352 + 4352)   /* 25088 floats = 100352 B */

__global__ __launch_bounds__(256)
void k_step(int t,
            const float* __restrict__ gi_cur_t,
            float* __restrict__ hring, float* __restrict__ gring,
            const float* __restrict__ Ws, const float* __restrict__ Qt,
            const float* __restrict__ r_vec, const float* __restrict__ b_ih,
            const float* __restrict__ b_hh, float* __restrict__ out_t)
{
    extern __shared__ float sm[];
    float* sW = sm + SMF_SW;
    float* sQ = sm + SMF_SQ;
    float* sd = sm + SMF_SD;
    float* hd = sm + SMF_HD;
    int tid = threadIdx.x;

    for (int i = tid; i < 64*192; i += 256) sW[i] = Ws[i];
    for (int i = tid; i < 64*64;  i += 256) sQ[i] = Qt[i];

    int slot = t % 3;
    int cg = tid & 31, nq = tid >> 5;       // GEMM mapping: 8 node-groups x 32 col-groups
    int j0 = 2*cg;
    int jA = tid & 63, ngA = tid >> 6;      // Phase-A mapping

    float2 bir = *(const float2*)&b_ih[j0];
    float2 biz = *(const float2*)&b_ih[64 + j0];
    float2 bin = *(const float2*)&b_ih[128 + j0];
    float2 bhr = *(const float2*)&b_hh[j0];
    float2 bhz = *(const float2*)&b_hh[64 + j0];
    float2 bhn = *(const float2*)&b_hh[128 + j0];
    float2 rv  = *(const float2*)&r_vec[j0];
    __syncthreads();

    for (int chunk = blockIdx.x; chunk*32 < NN; chunk += gridDim.x) {
        int base = chunk * 32;

        // -------- Phase A1: attention softmax + short = sum a_tau h_tau --------
        for (int ni = ngA; ni < 32; ni += 4) {
            int n = base + ni;
            float sv = 0.f;
            if (n < NN) {
                float e2 = (t >= 1) ? gring[((t-1)%3)*NN + n] : 0.0f;
                float e1 = (t >= 1) ? ((t >= 2) ? gring[((t-2)%3)*NN + n] : 0.0f) : -1e30f;
                float e0 = (t >= 2) ? ((t >= 3) ? gring[((t-3)%3)*NN + n] : 0.0f) : -1e30f;
                float mx = fmaxf(e2, fmaxf(e1, e0));
                float a0 = (t >= 2) ? __expf(e0 - mx) : 0.f;
                float a1 = (t >= 1) ? __expf(e1 - mx) : 0.f;
                float a2 = __expf(e2 - mx);
                float inv = 1.0f / (a0 + a1 + a2);
                if (t >= 3) sv += a0*inv * hring[(size_t)((t-3)%3)*NN*64 + (size_t)n*64 + jA];
                if (t >= 2) sv += a1*inv * hring[(size_t)((t-2)%3)*NN*64 + (size_t)n*64 + jA];
                if (t >= 1) sv += a2*inv * hring[(size_t)((t-1)%3)*NN*64 + (size_t)n*64 + jA];
            }
            sd[jA*68 + 2*ni]     = sv;
            sd[jA*68 + 2*ni + 1] = sv;
        }
        __syncthreads();

        // -------- Phase G1: gi_s = short @ Ws (gate-triple cols) fused with GRU --------
        {
            unsigned long long ar[4], az[4], an[4];
#pragma unroll
            for (int m = 0; m < 4; m++) { ar[m] = 0ull; az[m] = 0ull; an[m] = 0ull; }
#pragma unroll 8
            for (int k = 0; k < 64; k++) {
                ulonglong2 s01 = *(const ulonglong2*)&sd[k*68 + 8*nq];
                ulonglong2 s23 = *(const ulonglong2*)&sd[k*68 + 8*nq + 4];
                unsigned long long wr = *(const unsigned long long*)&sW[k*192 + j0];
                unsigned long long wz = *(const unsigned long long*)&sW[k*192 + 64 + j0];
                unsigned long long wn = *(const unsigned long long*)&sW[k*192 + 128 + j0];
                ffma2(ar[0], s01.x, wr); ffma2(az[0], s01.x, wz); ffma2(an[0], s01.x, wn);
                ffma2(ar[1], s01.y, wr); ffma2(az[1], s01.y, wz); ffma2(an[1], s01.y, wn);
                ffma2(ar[2], s23.x, wr); ffma2(az[2], s23.x, wz); ffma2(an[2], s23.x, wn);
                ffma2(ar[3], s23.y, wr); ffma2(az[3], s23.y, wz); ffma2(an[3], s23.y, wn);
            }
#pragma unroll
            for (int m = 0; m < 4; m++) {
                int ni = nq*4 + m;
                int n  = base + ni;
                float hx = 0.f, hy = 0.f;
                if (n < NN) {
                    const float* gc = &gi_cur_t[(size_t)n*192];
                    float2 gr = *(const float2*)&gc[j0];
                    float2 gz = *(const float2*)&gc[64 + j0];
                    float2 gn = *(const float2*)&gc[128 + j0];
                    float2 pr = u2f2(ar[m]);
                    float2 pz = u2f2(az[m]);
                    float2 pn = u2f2(an[m]);
                    float rx = sigf(pr.x + gr.x + bir.x + bhr.x);
                    float ry = sigf(pr.y + gr.y + bir.y + bhr.y);
                    float zx = sigf(pz.x + gz.x + biz.x + bhz.x);
                    float zy = sigf(pz.y + gz.y + biz.y + bhz.y);
                    float nx = tanhf(pn.x + gn.x + bin.x + rx*bhn.x);
                    float ny = tanhf(pn.y + gn.y + bin.y + ry*bhn.y);
                    hx = (1.0f - zx) * nx;
                    hy = (1.0f - zy) * ny;
                    *(float2*)&out_t[(size_t)n*64 + j0] = make_float2(hx, hy);
                    *(float2*)&hring[(size_t)slot*NN*64 + (size_t)n*64 + j0] = make_float2(hx, hy);
                }
                *(float2*)&hd[j0*68 + 2*ni]     = make_float2(hx, hx);
                *(float2*)&hd[(j0+1)*68 + 2*ni] = make_float2(hy, hy);
            }
        }
        __syncthreads();

        // -------- Phase G2: scores g = r . tanh(h @ Qt) --------
        {
            unsigned long long ac[4] = {0ull, 0ull, 0ull, 0ull};
#pragma unroll 8
            for (int k = 0; k < 64; k++) {
                ulonglong2 h01 = *(const ulonglong2*)&hd[k*68 + 8*nq];
                ulonglong2 h23 = *(const ulonglong2*)&hd[k*68 + 8*nq + 4];
                unsigned long long q = *(const unsigned long long*)&sQ[k*64 + j0];
                ffma2(ac[0], h01.x, q);
                ffma2(ac[1], h01.y, q);
                ffma2(ac[2], h23.x, q);
                ffma2(ac[3], h23.y, q);
            }
#pragma unroll
            for (int m = 0; m < 4; m++) {
                float2 u = u2f2(ac[m]);
                float part = rv.x*tanhf(u.x) + rv.y*tanhf(u.y);
                part += __shfl_down_sync(0xffffffffu, part, 16);
                part += __shfl_down_sync(0xffffffffu, part, 8);
                part += __shfl_down_sync(0xffffffffu, part, 4);
                part += __shfl_down_sync(0xffffffffu, part, 2);
                part += __shfl_down_sync(0xffffffffu, part, 1);
                if (cg == 0) {
                    int n = base + nq*4 + m;
                    if (n < NN) gring[slot*NN + n] = part;
                }
            }
        }
        __syncthreads();
    }
}

// ------------------------- launcher -------------------------
extern "C" void kernel_launch(void* const* d_in, const int* in_sizes, int n_in,
                              void* d_out, int out_size)
{
    const float* xs    = (const float*)d_in[0];
    const int*   ei    = (const int*)  d_in[1];
    const float* W_gcn = (const float*)d_in[2];
    const float* b_gcn = (const float*)d_in[3];
    const float* Q     = (const float*)d_in[4];
    const float* r_vec = (const float*)d_in[5];
    const float* W_ih  = (const float*)d_in[6];
    const float* b_ih  = (const float*)d_in[8];
    const float* b_hh  = (const float*)d_in[9];
    float* out = (float*)d_out;

    float *p_xw, *p_cur, *p_gic, *p_hr, *p_gr, *p_dinv, *p_WcT, *p_Ws, *p_Qt;
    int   *p_cnt, *p_fill, *p_rp, *p_eb, *p_bs;
    cudaGetSymbolAddress((void**)&p_xw,   d_xw);
    cudaGetSymbolAddress((void**)&p_cur,  d_cur);
    cudaGetSymbolAddress((void**)&p_gic,  d_gicur);
    cudaGetSymbolAddress((void**)&p_hr,   d_hring);
    cudaGetSymbolAddress((void**)&p_gr,   d_gring);
    cudaGetSymbolAddress((void**)&p_dinv, d_dinv);
    cudaGetSymbolAddress((void**)&p_WcT,  d_WcT);
    cudaGetSymbolAddress((void**)&p_Ws,   d_Ws);
    cudaGetSymbolAddress((void**)&p_Qt,   d_Qt);
    cudaGetSymbolAddress((void**)&p_cnt,  d_cnt);
    cudaGetSymbolAddress((void**)&p_fill, d_fill);
    cudaGetSymbolAddress((void**)&p_rp,   d_rowptr);
    cudaGetSymbolAddress((void**)&p_eb,   d_ebuf);
    cudaGetSymbolAddress((void**)&p_bs,   d_bsum);

    static int attr_done = 0;
    if (!attr_done) {
        cudaFuncSetAttribute(k_step, cudaFuncAttributeMaxDynamicSharedMemorySize,
                             SMF_TOT * (int)sizeof(float));
        attr_done = 1;
    }

    const int nsb = (TN + 1023) / 1024;   // 586 scan blocks

    k_prep <<<1, 256>>>(W_ih, Q, p_WcT, p_Ws, p_Qt);
    cudaMemsetAsync(p_cnt, 0, (size_t)TN * sizeof(int));
    k_count<<<dim3((EE + 255)/256, TT), 256>>>(ei, p_cnt);

    // xw = xs @ W_gcn   [600000,128]x[128,64]
    k_gemm <<<dim3((TN + BM - 1)/BM, 1), 128>>>(xs, W_gcn, p_xw, TN, FIN, HH);

    k_scan1<<<nsb, 1024>>>(p_cnt, p_rp, p_bs, TN);
    k_scan2<<<1, 1024>>>(p_bs, nsb);
    k_scan3<<<nsb, 1024>>>(p_cnt, p_rp, p_bs, p_fill, p_dinv, TN);
    k_fill <<<dim3((EE + 255)/256, TT), 256>>>(ei, p_fill, p_eb);

    k_gather<<<(TN + 7)/8, 256>>>(p_xw, b_gcn, p_cur, p_rp, p_cnt, p_dinv, p_eb);

    // gi_cur = cur @ W_c^T   [600000,64]x[64,192]
    k_gemm <<<dim3((TN + BM - 1)/BM, 3), 128>>>(p_cur, p_WcT, p_gic, TN, HH, 192);

    for (int t = 0; t < TT; t++) {
        k_step<<<296, 256, SMF_TOT * (int)sizeof(float)>>>(
            t, p_gic + (size_t)t*NN*192, p_hr, p_gr,
            p_Ws, p_Qt, r_vec, b_ih, b_hh,
            out + (size_t)t*NN*64);
    }
}